// round 2
// baseline (speedup 1.0000x reference)
#include <cuda_runtime.h>
#include <math.h>

#define NN 50000
#define NE 800000
#define HD 64
#define NC 10

// ---------------- scratch (device globals; no allocations allowed) ------------
__device__ __align__(256) float gA[NN * HD];
__device__ __align__(256) float gB[NN * HD];
__device__ __align__(256) float gC[NN * NC];
__device__ int g_csrc[NE];      // CSR-ordered source node per slot
__device__ float g_cw[NE];      // CSR-ordered edge weight per slot
__device__ int g_rowptr[NN + 1];
__device__ int g_fillpos[NN];
__device__ int g_deg[NN];
__device__ int g_is64;

// ---------------- edge index dtype detect ------------------------------------
__global__ void detect_k(const void* ei) {
    if (threadIdx.x == 0 && blockIdx.x == 0) {
        const long long* p = (const long long*)ei;
        int ok = 1;
        for (int i = 0; i < 1024; i++) {
            long long v = p[i];
            if (v < 0 || v >= NN) { ok = 0; break; }
        }
        g_is64 = ok;
    }
}

__global__ void zerodeg_k() {
    int i = blockIdx.x * blockDim.x + threadIdx.x;
    if (i < NN) g_deg[i] = 0;
}

// histogram of destination degrees (edges kept in original layout for now)
__global__ void hist_k(const void* ei) {
    int i = blockIdx.x * blockDim.x + threadIdx.x;
    if (i >= NE) return;
    int d;
    if (g_is64) d = (int)((const long long*)ei)[NE + i];
    else        d = ((const int*)ei)[NE + i];
    atomicAdd(&g_deg[d], 1);
}

// single-block scan of degrees -> row_ptr, fill_pos
__global__ void __launch_bounds__(1024) scan_k() {
    __shared__ int s[1024];
    const int CH = (NN + 1023) / 1024;  // 49
    int t = threadIdx.x;
    int base = t * CH;
    int sum = 0;
    for (int i = 0; i < CH; i++) {
        int idx = base + i;
        if (idx < NN) sum += g_deg[idx];
    }
    s[t] = sum;
    __syncthreads();
    for (int off = 1; off < 1024; off <<= 1) {
        int v = (t >= off) ? s[t - off] : 0;
        __syncthreads();
        s[t] += v;
        __syncthreads();
    }
    int run = (t == 0) ? 0 : s[t - 1];
    for (int i = 0; i < CH; i++) {
        int idx = base + i;
        if (idx < NN) {
            g_rowptr[idx] = run;
            g_fillpos[idx] = run;
            run += g_deg[idx];
        }
    }
    if (t == 1023) g_rowptr[NN] = run;
}

// scatter edges into CSR slots
__global__ void fill_k(const void* ei, const float* __restrict__ ew) {
    int i = blockIdx.x * blockDim.x + threadIdx.x;
    if (i >= NE) return;
    int sidx, d;
    if (g_is64) {
        const long long* p = (const long long*)ei;
        sidx = (int)p[i];
        d = (int)p[NE + i];
    } else {
        const int* p = (const int*)ei;
        sidx = p[i];
        d = p[NE + i];
    }
    int pos = atomicAdd(&g_fillpos[d], 1);
    g_csrc[pos] = sidx;
    g_cw[pos] = ew[i];
}

// ---------------- GEMM: [NN,64] @ [64,64], 16 acc per thread ------------------
__global__ void __launch_bounds__(256) gemm64_k(const float* __restrict__ in,
                                                const float* __restrict__ W,
                                                float* __restrict__ out) {
    __shared__ float Ws[64 * 64];
    __shared__ float Xs[64 * 64];
    int t = threadIdx.x;
    int row0 = blockIdx.x * 64;
    for (int i = t; i < 4096; i += 256) Ws[i] = W[i];
    for (int i = t; i < 4096; i += 256) {
        int r = row0 + (i >> 6);
        Xs[i] = (r < NN) ? in[r * 64 + (i & 63)] : 0.f;
    }
    __syncthreads();
    int col = t & 63;
    int rq = t >> 6;  // 0..3
    float acc[16];
    #pragma unroll
    for (int i = 0; i < 16; i++) acc[i] = 0.f;
    #pragma unroll 8
    for (int k = 0; k < 64; k++) {
        float w = Ws[k * 64 + col];
        #pragma unroll
        for (int i = 0; i < 16; i++)
            acc[i] = fmaf(Xs[(rq + 4 * i) * 64 + k], w, acc[i]);
    }
    #pragma unroll
    for (int i = 0; i < 16; i++) {
        int r = row0 + rq + 4 * i;
        if (r < NN) out[r * 64 + col] = acc[i];
    }
}

// ---------------- GEMM: [NN,64] @ [64,10] -------------------------------------
__global__ void __launch_bounds__(640) gemm10_k(const float* __restrict__ in,
                                                const float* __restrict__ W,
                                                float* __restrict__ out) {
    __shared__ float Ws[64 * NC];
    __shared__ float Xs[64 * 64];
    int t = threadIdx.x;
    int row0 = blockIdx.x * 64;
    for (int i = t; i < 64 * NC; i += 640) Ws[i] = W[i];
    for (int i = t; i < 4096; i += 640) {
        int r = row0 + (i >> 6);
        Xs[i] = (r < NN) ? in[r * 64 + (i & 63)] : 0.f;
    }
    __syncthreads();
    int row = t / NC;
    int col = t - row * NC;
    int r = row0 + row;
    if (r >= NN) return;
    float s = 0.f;
    #pragma unroll
    for (int k = 0; k < 64; k++) s = fmaf(Xs[row * 64 + k], Ws[k * NC + col], s);
    out[r * NC + col] = s;
}

// ------- fused gather-aggregate (64ch) + bias + softmax: warp per node --------
__global__ void __launch_bounds__(256) agg64sm_k(const float* __restrict__ h,
                                                 const float* __restrict__ b,
                                                 float* __restrict__ out) {
    int node = (blockIdx.x * blockDim.x + threadIdx.x) >> 5;
    int lane = threadIdx.x & 31;
    if (node >= NN) return;
    int start = g_rowptr[node];
    int end = g_rowptr[node + 1];
    float a0 = __ldg(&b[lane]);
    float a1 = __ldg(&b[lane + 32]);
    for (int j0 = start; j0 < end; j0 += 32) {
        int j = j0 + lane;
        int s = 0; float w = 0.f;
        if (j < end) { s = g_csrc[j]; w = g_cw[j]; }
        int cnt = min(32, end - j0);
        for (int q = 0; q < cnt; q++) {
            int ss = __shfl_sync(0xFFFFFFFFu, s, q);
            float ww = __shfl_sync(0xFFFFFFFFu, w, q);
            a0 = fmaf(__ldg(&h[ss * 64 + lane]), ww, a0);
            a1 = fmaf(__ldg(&h[ss * 64 + 32 + lane]), ww, a1);
        }
    }
    // in-warp softmax over 64 channels
    float m = fmaxf(a0, a1);
    #pragma unroll
    for (int o = 16; o; o >>= 1) m = fmaxf(m, __shfl_xor_sync(0xFFFFFFFFu, m, o));
    float e0 = __expf(a0 - m);
    float e1 = __expf(a1 - m);
    float sm = e0 + e1;
    #pragma unroll
    for (int o = 16; o; o >>= 1) sm += __shfl_xor_sync(0xFFFFFFFFu, sm, o);
    float inv = 1.f / sm;
    out[node * 64 + lane] = e0 * inv;
    out[node * 64 + 32 + lane] = e1 * inv;
}

// ------- fused gather-aggregate (10ch) + bias + softmax: warp per node --------
__global__ void __launch_bounds__(256) agg10sm_k(const float* __restrict__ h,
                                                 const float* __restrict__ b,
                                                 float* __restrict__ out) {
    int node = (blockIdx.x * blockDim.x + threadIdx.x) >> 5;
    int lane = threadIdx.x & 31;
    if (node >= NN) return;
    int start = g_rowptr[node];
    int end = g_rowptr[node + 1];
    float a = (lane < NC) ? __ldg(&b[lane]) : -INFINITY;
    for (int j0 = start; j0 < end; j0 += 32) {
        int j = j0 + lane;
        int s = 0; float w = 0.f;
        if (j < end) { s = g_csrc[j]; w = g_cw[j]; }
        int cnt = min(32, end - j0);
        for (int q = 0; q < cnt; q++) {
            int ss = __shfl_sync(0xFFFFFFFFu, s, q);
            float ww = __shfl_sync(0xFFFFFFFFu, w, q);
            if (lane < NC) a = fmaf(__ldg(&h[ss * NC + lane]), ww, a);
        }
    }
    // softmax over 10 lanes
    float m = a;
    #pragma unroll
    for (int o = 16; o; o >>= 1) m = fmaxf(m, __shfl_xor_sync(0xFFFFFFFFu, m, o));
    float e = (lane < NC) ? __expf(a - m) : 0.f;
    float sm = e;
    #pragma unroll
    for (int o = 16; o; o >>= 1) sm += __shfl_xor_sync(0xFFFFFFFFu, sm, o);
    if (lane < NC) out[node * NC + lane] = e / sm;
}

// ---------------- launch ------------------------------------------------------
extern "C" void kernel_launch(void* const* d_in, const int* in_sizes, int n_in,
                              void* d_out, int out_size) {
    const float* x  = (const float*)d_in[0];
    const void*  ei = d_in[1];
    const float* ew = (const float*)d_in[2];
    const float* W0 = (const float*)d_in[3];
    const float* b0 = (const float*)d_in[4];
    const float* W1 = (const float*)d_in[5];
    const float* b1 = (const float*)d_in[6];
    const float* W2 = (const float*)d_in[7];
    const float* b2 = (const float*)d_in[8];
    float* out = (float*)d_out;

    float *A, *B, *C;
    cudaGetSymbolAddress((void**)&A, gA);
    cudaGetSymbolAddress((void**)&B, gB);
    cudaGetSymbolAddress((void**)&C, gC);

    const int rowBlocks = (NN + 63) / 64;
    const int nodeWarpBlocks = (NN * 32 + 255) / 256;

    // ---- CSR build ----
    detect_k<<<1, 1>>>(ei);
    zerodeg_k<<<(NN + 255) / 256, 256>>>();
    hist_k<<<(NE + 255) / 256, 256>>>(ei);
    scan_k<<<1, 1024>>>();
    fill_k<<<(NE + 255) / 256, 256>>>(ei, ew);

    // ---- Layer 0: h = x@W0 ; agg+b0+softmax ----
    gemm64_k<<<rowBlocks, 256>>>(x, W0, A);
    agg64sm_k<<<nodeWarpBlocks, 256>>>(A, b0, B);

    // ---- Layer 1 ----
    gemm64_k<<<rowBlocks, 256>>>(B, W1, A);
    agg64sm_k<<<nodeWarpBlocks, 256>>>(A, b1, B);

    // ---- Layer 2 (64 -> 10) ----
    gemm10_k<<<rowBlocks, 640>>>(B, W2, C);
    agg10sm_k<<<nodeWarpBlocks, 256>>>(C, b2, out);
}

// round 3
// speedup vs baseline: 1.4027x; 1.4027x over previous
#include <cuda_runtime.h>
#include <math.h>

#define NN 50000
#define NE 800000
#define HD 64
#define NC 10
#define SCAN_B 1024
#define SCAN_G ((NN + SCAN_B - 1) / SCAN_B)   // 49

// ---------------- scratch (device globals; no allocations allowed) ------------
__device__ __align__(256) float gA[NN * HD];
__device__ __align__(256) float gB[NN * HD];
__device__ __align__(256) float gC[NN * NC];
__device__ int g_csrc[NE];      // CSR-ordered source node per slot
__device__ float g_cw[NE];      // CSR-ordered edge weight per slot
__device__ int g_rowptr[NN + 1];
__device__ int g_fillpos[NN];
__device__ int g_deg[NN];
__device__ int g_part[SCAN_G];
__device__ int g_is64;

// ---------------- edge index dtype detect ------------------------------------
__global__ void detect_k(const void* ei) {
    if (threadIdx.x == 0 && blockIdx.x == 0) {
        const long long* p = (const long long*)ei;
        int ok = 1;
        for (int i = 0; i < 1024; i++) {
            long long v = p[i];
            if (v < 0 || v >= NN) { ok = 0; break; }
        }
        g_is64 = ok;
    }
}

__global__ void zerodeg_k() {
    int i = blockIdx.x * blockDim.x + threadIdx.x;
    if (i < NN) g_deg[i] = 0;
}

// histogram of destination degrees
__global__ void hist_k(const void* ei) {
    int i = blockIdx.x * blockDim.x + threadIdx.x;
    if (i >= NE) return;
    int d;
    if (g_is64) d = (int)((const long long*)ei)[NE + i];
    else        d = ((const int*)ei)[NE + i];
    atomicAdd(&g_deg[d], 1);
}

// ---- scan stage 1: per-block sums -------------------------------------------
__global__ void __launch_bounds__(SCAN_B) blocksum_k() {
    __shared__ int s[32];
    int idx = blockIdx.x * SCAN_B + threadIdx.x;
    int v = (idx < NN) ? g_deg[idx] : 0;
    #pragma unroll
    for (int o = 16; o; o >>= 1) v += __shfl_xor_sync(0xFFFFFFFFu, v, o);
    int lane = threadIdx.x & 31, warp = threadIdx.x >> 5;
    if (lane == 0) s[warp] = v;
    __syncthreads();
    if (warp == 0) {
        int w = s[lane];
        #pragma unroll
        for (int o = 16; o; o >>= 1) w += __shfl_xor_sync(0xFFFFFFFFu, w, o);
        if (lane == 0) g_part[blockIdx.x] = w;
    }
}

// ---- scan stage 2: exclusive scan of SCAN_G partials (one warp+) -------------
__global__ void scanpart_k() {
    __shared__ int s[64];
    int t = threadIdx.x;
    s[t] = (t < SCAN_G) ? g_part[t] : 0;
    __syncthreads();
    for (int off = 1; off < 64; off <<= 1) {
        int v = (t >= off) ? s[t - off] : 0;
        __syncthreads();
        s[t] += v;
        __syncthreads();
    }
    if (t < SCAN_G) g_part[t] = (t == 0) ? 0 : s[t - 1];
}

// ---- scan stage 3: per-block exclusive scan + offset --------------------------
__global__ void __launch_bounds__(SCAN_B) blockscan_k() {
    __shared__ int s[SCAN_B];
    int t = threadIdx.x;
    int idx = blockIdx.x * SCAN_B + t;
    int v = (idx < NN) ? g_deg[idx] : 0;
    s[t] = v;
    __syncthreads();
    #pragma unroll
    for (int off = 1; off < SCAN_B; off <<= 1) {
        int u = (t >= off) ? s[t - off] : 0;
        __syncthreads();
        s[t] += u;
        __syncthreads();
    }
    if (idx < NN) {
        int excl = g_part[blockIdx.x] + s[t] - v;  // exclusive prefix
        g_rowptr[idx] = excl;
        g_fillpos[idx] = excl;
    }
    if (blockIdx.x == 0 && t == 0) g_rowptr[NN] = NE;
}

// scatter edges into CSR slots
__global__ void fill_k(const void* ei, const float* __restrict__ ew) {
    int i = blockIdx.x * blockDim.x + threadIdx.x;
    if (i >= NE) return;
    int sidx, d;
    if (g_is64) {
        const long long* p = (const long long*)ei;
        sidx = (int)p[i];
        d = (int)p[NE + i];
    } else {
        const int* p = (const int*)ei;
        sidx = p[i];
        d = p[NE + i];
    }
    int pos = atomicAdd(&g_fillpos[d], 1);
    g_csrc[pos] = sidx;
    g_cw[pos] = ew[i];
}

// ---------------- GEMM: [NN,64] @ [64,64], 16 acc per thread ------------------
__global__ void __launch_bounds__(256) gemm64_k(const float* __restrict__ in,
                                                const float* __restrict__ W,
                                                float* __restrict__ out) {
    __shared__ float Ws[64 * 64];
    __shared__ float Xs[64 * 64];
    int t = threadIdx.x;
    int row0 = blockIdx.x * 64;
    for (int i = t; i < 4096; i += 256) Ws[i] = W[i];
    for (int i = t; i < 4096; i += 256) {
        int r = row0 + (i >> 6);
        Xs[i] = (r < NN) ? in[r * 64 + (i & 63)] : 0.f;
    }
    __syncthreads();
    int col = t & 63;
    int rq = t >> 6;  // 0..3
    float acc[16];
    #pragma unroll
    for (int i = 0; i < 16; i++) acc[i] = 0.f;
    #pragma unroll 8
    for (int k = 0; k < 64; k++) {
        float w = Ws[k * 64 + col];
        #pragma unroll
        for (int i = 0; i < 16; i++)
            acc[i] = fmaf(Xs[(rq + 4 * i) * 64 + k], w, acc[i]);
    }
    #pragma unroll
    for (int i = 0; i < 16; i++) {
        int r = row0 + rq + 4 * i;
        if (r < NN) out[r * 64 + col] = acc[i];
    }
}

// ---------------- GEMM: [NN,64] @ [64,10] -------------------------------------
__global__ void __launch_bounds__(640) gemm10_k(const float* __restrict__ in,
                                                const float* __restrict__ W,
                                                float* __restrict__ out) {
    __shared__ float Ws[64 * NC];
    __shared__ float Xs[64 * 64];
    int t = threadIdx.x;
    int row0 = blockIdx.x * 64;
    for (int i = t; i < 64 * NC; i += 640) Ws[i] = W[i];
    for (int i = t; i < 4096; i += 640) {
        int r = row0 + (i >> 6);
        Xs[i] = (r < NN) ? in[r * 64 + (i & 63)] : 0.f;
    }
    __syncthreads();
    int row = t / NC;
    int col = t - row * NC;
    int r = row0 + row;
    if (r >= NN) return;
    float s = 0.f;
    #pragma unroll
    for (int k = 0; k < 64; k++) s = fmaf(Xs[row * 64 + k], Ws[k * NC + col], s);
    out[r * NC + col] = s;
}

// ------- fused gather-aggregate (64ch) + bias + softmax: warp per node --------
__global__ void __launch_bounds__(256) agg64sm_k(const float* __restrict__ h,
                                                 const float* __restrict__ b,
                                                 float* __restrict__ out) {
    int node = (blockIdx.x * blockDim.x + threadIdx.x) >> 5;
    int lane = threadIdx.x & 31;
    if (node >= NN) return;
    int start = g_rowptr[node];
    int end = g_rowptr[node + 1];
    float a0 = __ldg(&b[lane]);
    float a1 = __ldg(&b[lane + 32]);
    for (int j0 = start; j0 < end; j0 += 32) {
        int j = j0 + lane;
        int s = 0; float w = 0.f;
        if (j < end) { s = g_csrc[j]; w = g_cw[j]; }
        int cnt = min(32, end - j0);
        for (int q = 0; q < cnt; q++) {
            int ss = __shfl_sync(0xFFFFFFFFu, s, q);
            float ww = __shfl_sync(0xFFFFFFFFu, w, q);
            a0 = fmaf(__ldg(&h[ss * 64 + lane]), ww, a0);
            a1 = fmaf(__ldg(&h[ss * 64 + 32 + lane]), ww, a1);
        }
    }
    // in-warp softmax over 64 channels
    float m = fmaxf(a0, a1);
    #pragma unroll
    for (int o = 16; o; o >>= 1) m = fmaxf(m, __shfl_xor_sync(0xFFFFFFFFu, m, o));
    float e0 = __expf(a0 - m);
    float e1 = __expf(a1 - m);
    float sm = e0 + e1;
    #pragma unroll
    for (int o = 16; o; o >>= 1) sm += __shfl_xor_sync(0xFFFFFFFFu, sm, o);
    float inv = 1.f / sm;
    out[node * 64 + lane] = e0 * inv;
    out[node * 64 + 32 + lane] = e1 * inv;
}

// ------- fused gather-aggregate (10ch) + bias + softmax: warp per node --------
__global__ void __launch_bounds__(256) agg10sm_k(const float* __restrict__ h,
                                                 const float* __restrict__ b,
                                                 float* __restrict__ out) {
    int node = (blockIdx.x * blockDim.x + threadIdx.x) >> 5;
    int lane = threadIdx.x & 31;
    if (node >= NN) return;
    int start = g_rowptr[node];
    int end = g_rowptr[node + 1];
    float a = (lane < NC) ? __ldg(&b[lane]) : -INFINITY;
    for (int j0 = start; j0 < end; j0 += 32) {
        int j = j0 + lane;
        int s = 0; float w = 0.f;
        if (j < end) { s = g_csrc[j]; w = g_cw[j]; }
        int cnt = min(32, end - j0);
        for (int q = 0; q < cnt; q++) {
            int ss = __shfl_sync(0xFFFFFFFFu, s, q);
            float ww = __shfl_sync(0xFFFFFFFFu, w, q);
            if (lane < NC) a = fmaf(__ldg(&h[ss * NC + lane]), ww, a);
        }
    }
    // softmax over 10 lanes
    float m = a;
    #pragma unroll
    for (int o = 16; o; o >>= 1) m = fmaxf(m, __shfl_xor_sync(0xFFFFFFFFu, m, o));
    float e = (lane < NC) ? __expf(a - m) : 0.f;
    float sm = e;
    #pragma unroll
    for (int o = 16; o; o >>= 1) sm += __shfl_xor_sync(0xFFFFFFFFu, sm, o);
    if (lane < NC) out[node * NC + lane] = e / sm;
}

// ---------------- launch ------------------------------------------------------
extern "C" void kernel_launch(void* const* d_in, const int* in_sizes, int n_in,
                              void* d_out, int out_size) {
    const float* x  = (const float*)d_in[0];
    const void*  ei = d_in[1];
    const float* ew = (const float*)d_in[2];
    const float* W0 = (const float*)d_in[3];
    const float* b0 = (const float*)d_in[4];
    const float* W1 = (const float*)d_in[5];
    const float* b1 = (const float*)d_in[6];
    const float* W2 = (const float*)d_in[7];
    const float* b2 = (const float*)d_in[8];
    float* out = (float*)d_out;

    float *A, *B, *C;
    cudaGetSymbolAddress((void**)&A, gA);
    cudaGetSymbolAddress((void**)&B, gB);
    cudaGetSymbolAddress((void**)&C, gC);

    const int rowBlocks = (NN + 63) / 64;
    const int nodeWarpBlocks = (NN * 32 + 255) / 256;

    // ---- CSR build ----
    detect_k<<<1, 1>>>(ei);
    zerodeg_k<<<(NN + 255) / 256, 256>>>();
    hist_k<<<(NE + 255) / 256, 256>>>(ei);
    blocksum_k<<<SCAN_G, SCAN_B>>>();
    scanpart_k<<<1, 64>>>();
    blockscan_k<<<SCAN_G, SCAN_B>>>();
    fill_k<<<(NE + 255) / 256, 256>>>(ei, ew);

    // ---- Layer 0: h = x@W0 ; agg+b0+softmax ----
    gemm64_k<<<rowBlocks, 256>>>(x, W0, A);
    agg64sm_k<<<nodeWarpBlocks, 256>>>(A, b0, B);

    // ---- Layer 1 ----
    gemm64_k<<<rowBlocks, 256>>>(B, W1, A);
    agg64sm_k<<<nodeWarpBlocks, 256>>>(A, b1, B);

    // ---- Layer 2 (64 -> 10) ----
    gemm10_k<<<rowBlocks, 640>>>(B, W2, C);
    agg10sm_k<<<nodeWarpBlocks, 256>>>(C, b2, out);
}

// round 5
// speedup vs baseline: 1.4857x; 1.0592x over previous
#include <cuda_runtime.h>
#include <math.h>

#define NN 50000
#define NE 800000
#define HD 64
#define NC 10
#define SCAN_B 1024
#define SCAN_G ((NN + SCAN_B - 1) / SCAN_B)   // 49

// ---------------- scratch (device globals; no allocations allowed) ------------
__device__ __align__(256) float gA[NN * HD];
__device__ __align__(256) float gB[NN * HD];
__device__ __align__(256) float gC[NN * NC];
__device__ __align__(256) int2 g_ep[NE];   // packed (src, weight-bits), CSR order
__device__ int g_rowptr[NN + 1];
__device__ int g_fillpos[NN];
__device__ int g_deg[NN];
__device__ int g_part[SCAN_G];
__device__ int g_is64;

// ---------------- edge index dtype detect (R3-verbatim) -----------------------
__global__ void detect_k(const void* ei) {
    if (threadIdx.x == 0 && blockIdx.x == 0) {
        const long long* p = (const long long*)ei;
        int ok = 1;
        for (int i = 0; i < 1024; i++) {
            long long v = p[i];
            if (v < 0 || v >= NN) { ok = 0; break; }
        }
        g_is64 = ok;
    }
}

__global__ void zerodeg_k() {
    int i = blockIdx.x * blockDim.x + threadIdx.x;
    if (i < NN) g_deg[i] = 0;
}

// histogram of destination degrees
__global__ void hist_k(const void* ei) {
    int i = blockIdx.x * blockDim.x + threadIdx.x;
    if (i >= NE) return;
    int d;
    if (g_is64) d = (int)((const long long*)ei)[NE + i];
    else        d = ((const int*)ei)[NE + i];
    atomicAdd(&g_deg[d], 1);
}

// ---- scan stage 1: per-block sums -------------------------------------------
__global__ void __launch_bounds__(SCAN_B) blocksum_k() {
    __shared__ int s[32];
    int idx = blockIdx.x * SCAN_B + threadIdx.x;
    int v = (idx < NN) ? g_deg[idx] : 0;
    #pragma unroll
    for (int o = 16; o; o >>= 1) v += __shfl_xor_sync(0xFFFFFFFFu, v, o);
    int lane = threadIdx.x & 31, warp = threadIdx.x >> 5;
    if (lane == 0) s[warp] = v;
    __syncthreads();
    if (warp == 0) {
        int w = s[lane];
        #pragma unroll
        for (int o = 16; o; o >>= 1) w += __shfl_xor_sync(0xFFFFFFFFu, w, o);
        if (lane == 0) g_part[blockIdx.x] = w;
    }
}

// ---- scan stage 2: per-block scan; each block redundantly scans partials -----
__global__ void __launch_bounds__(SCAN_B) blockscan_k() {
    __shared__ int parts[64];
    __shared__ int s[SCAN_B];
    int t = threadIdx.x;
    if (t < 64) parts[t] = (t < SCAN_G) ? g_part[t] : 0;
    __syncthreads();
    #pragma unroll
    for (int off = 1; off < 64; off <<= 1) {
        int v = (t < 64 && t >= off) ? parts[t - off] : 0;
        __syncthreads();
        if (t < 64) parts[t] += v;
        __syncthreads();
    }
    int blockoff = (blockIdx.x == 0) ? 0 : parts[blockIdx.x - 1];

    int idx = blockIdx.x * SCAN_B + t;
    int v = (idx < NN) ? g_deg[idx] : 0;
    s[t] = v;
    __syncthreads();
    #pragma unroll
    for (int off = 1; off < SCAN_B; off <<= 1) {
        int u = (t >= off) ? s[t - off] : 0;
        __syncthreads();
        s[t] += u;
        __syncthreads();
    }
    if (idx < NN) {
        int excl = blockoff + s[t] - v;
        g_rowptr[idx] = excl;
        g_fillpos[idx] = excl;
    }
    if (blockIdx.x == 0 && t == 0) g_rowptr[NN] = NE;
}

// scatter edges into packed CSR slots
__global__ void fill_k(const void* ei, const float* __restrict__ ew) {
    int i = blockIdx.x * blockDim.x + threadIdx.x;
    if (i >= NE) return;
    int sidx, d;
    if (g_is64) {
        const long long* p = (const long long*)ei;
        sidx = (int)p[i];
        d = (int)p[NE + i];
    } else {
        const int* p = (const int*)ei;
        sidx = p[i];
        d = p[NE + i];
    }
    int pos = atomicAdd(&g_fillpos[d], 1);
    g_ep[pos] = make_int2(sidx, __float_as_int(ew[i]));
}

// ---------------- GEMM: [NN,64] @ [64,64], 16 acc per thread (R3-verbatim) ----
__global__ void __launch_bounds__(256) gemm64_k(const float* __restrict__ in,
                                                const float* __restrict__ W,
                                                float* __restrict__ out) {
    __shared__ float Ws[64 * 64];
    __shared__ float Xs[64 * 64];
    int t = threadIdx.x;
    int row0 = blockIdx.x * 64;
    for (int i = t; i < 4096; i += 256) Ws[i] = W[i];
    for (int i = t; i < 4096; i += 256) {
        int r = row0 + (i >> 6);
        Xs[i] = (r < NN) ? in[r * 64 + (i & 63)] : 0.f;
    }
    __syncthreads();
    int col = t & 63;
    int rq = t >> 6;  // 0..3
    float acc[16];
    #pragma unroll
    for (int i = 0; i < 16; i++) acc[i] = 0.f;
    #pragma unroll 8
    for (int k = 0; k < 64; k++) {
        float w = Ws[k * 64 + col];
        #pragma unroll
        for (int i = 0; i < 16; i++)
            acc[i] = fmaf(Xs[(rq + 4 * i) * 64 + k], w, acc[i]);
    }
    #pragma unroll
    for (int i = 0; i < 16; i++) {
        int r = row0 + rq + 4 * i;
        if (r < NN) out[r * 64 + col] = acc[i];
    }
}

// ---------------- GEMM: [NN,64] @ [64,10] (R3-verbatim) -----------------------
__global__ void __launch_bounds__(640) gemm10_k(const float* __restrict__ in,
                                                const float* __restrict__ W,
                                                float* __restrict__ out) {
    __shared__ float Ws[64 * NC];
    __shared__ float Xs[64 * 64];
    int t = threadIdx.x;
    int row0 = blockIdx.x * 64;
    for (int i = t; i < 64 * NC; i += 640) Ws[i] = W[i];
    for (int i = t; i < 4096; i += 640) {
        int r = row0 + (i >> 6);
        Xs[i] = (r < NN) ? in[r * 64 + (i & 63)] : 0.f;
    }
    __syncthreads();
    int row = t / NC;
    int col = t - row * NC;
    int r = row0 + row;
    if (r >= NN) return;
    float s = 0.f;
    #pragma unroll
    for (int k = 0; k < 64; k++) s = fmaf(Xs[row * 64 + k], Ws[k * NC + col], s);
    out[r * NC + col] = s;
}

// ------- fused gather-aggregate (64ch) + bias + softmax: warp per node --------
// float2 feature loads (plain generic LDG.64), int2 packed edges, 2-edge unroll.
__global__ void __launch_bounds__(256) agg64sm_k(const float2* __restrict__ h2,
                                                 const float* __restrict__ b,
                                                 float2* __restrict__ out2) {
    int node = (blockIdx.x * blockDim.x + threadIdx.x) >> 5;
    int lane = threadIdx.x & 31;
    if (node >= NN) return;
    int start = g_rowptr[node];
    int end = g_rowptr[node + 1];
    float ax0 = b[lane * 2], ay0 = b[lane * 2 + 1];
    float ax1 = 0.f, ay1 = 0.f;
    for (int j0 = start; j0 < end; j0 += 32) {
        int j = j0 + lane;
        int sx = 0, wy = 0;
        if (j < end) { int2 ep = g_ep[j]; sx = ep.x; wy = ep.y; }
        int cnt = min(32, end - j0);
        int q = 0;
        for (; q + 2 <= cnt; q += 2) {
            int s0 = __shfl_sync(0xFFFFFFFFu, sx, q);
            float w0 = __int_as_float(__shfl_sync(0xFFFFFFFFu, wy, q));
            int s1 = __shfl_sync(0xFFFFFFFFu, sx, q + 1);
            float w1 = __int_as_float(__shfl_sync(0xFFFFFFFFu, wy, q + 1));
            float2 v0 = h2[s0 * 32 + lane];
            float2 v1 = h2[s1 * 32 + lane];
            ax0 = fmaf(v0.x, w0, ax0); ay0 = fmaf(v0.y, w0, ay0);
            ax1 = fmaf(v1.x, w1, ax1); ay1 = fmaf(v1.y, w1, ay1);
        }
        if (q < cnt) {
            int s0 = __shfl_sync(0xFFFFFFFFu, sx, q);
            float w0 = __int_as_float(__shfl_sync(0xFFFFFFFFu, wy, q));
            float2 v0 = h2[s0 * 32 + lane];
            ax0 = fmaf(v0.x, w0, ax0); ay0 = fmaf(v0.y, w0, ay0);
        }
    }
    float a0 = ax0 + ax1, a1 = ay0 + ay1;
    // softmax over the 64 channels held pairwise across the warp
    float m = fmaxf(a0, a1);
    #pragma unroll
    for (int o = 16; o; o >>= 1) m = fmaxf(m, __shfl_xor_sync(0xFFFFFFFFu, m, o));
    float e0 = __expf(a0 - m);
    float e1 = __expf(a1 - m);
    float sm = e0 + e1;
    #pragma unroll
    for (int o = 16; o; o >>= 1) sm += __shfl_xor_sync(0xFFFFFFFFu, sm, o);
    float inv = 1.f / sm;
    out2[node * 32 + lane] = make_float2(e0 * inv, e1 * inv);
}

// ------- fused gather-aggregate (10ch) + bias + softmax (R3 structure) --------
__global__ void __launch_bounds__(256) agg10sm_k(const float* __restrict__ h,
                                                 const float* __restrict__ b,
                                                 float* __restrict__ out) {
    int node = (blockIdx.x * blockDim.x + threadIdx.x) >> 5;
    int lane = threadIdx.x & 31;
    if (node >= NN) return;
    int start = g_rowptr[node];
    int end = g_rowptr[node + 1];
    float a = (lane < NC) ? b[lane] : -INFINITY;
    for (int j0 = start; j0 < end; j0 += 32) {
        int j = j0 + lane;
        int sx = 0, wy = 0;
        if (j < end) { int2 ep = g_ep[j]; sx = ep.x; wy = ep.y; }
        int cnt = min(32, end - j0);
        for (int q = 0; q < cnt; q++) {
            int ss = __shfl_sync(0xFFFFFFFFu, sx, q);
            float ww = __int_as_float(__shfl_sync(0xFFFFFFFFu, wy, q));
            if (lane < NC) a = fmaf(h[ss * NC + lane], ww, a);
        }
    }
    float m = a;
    #pragma unroll
    for (int o = 16; o; o >>= 1) m = fmaxf(m, __shfl_xor_sync(0xFFFFFFFFu, m, o));
    float e = (lane < NC) ? __expf(a - m) : 0.f;
    float sm = e;
    #pragma unroll
    for (int o = 16; o; o >>= 1) sm += __shfl_xor_sync(0xFFFFFFFFu, sm, o);
    if (lane < NC) out[node * NC + lane] = e / sm;
}

// ---------------- launch ------------------------------------------------------
extern "C" void kernel_launch(void* const* d_in, const int* in_sizes, int n_in,
                              void* d_out, int out_size) {
    const float* x  = (const float*)d_in[0];
    const void*  ei = d_in[1];
    const float* ew = (const float*)d_in[2];
    const float* W0 = (const float*)d_in[3];
    const float* b0 = (const float*)d_in[4];
    const float* W1 = (const float*)d_in[5];
    const float* b1 = (const float*)d_in[6];
    const float* W2 = (const float*)d_in[7];
    const float* b2 = (const float*)d_in[8];
    float* out = (float*)d_out;

    float *A, *B, *C;
    cudaGetSymbolAddress((void**)&A, gA);
    cudaGetSymbolAddress((void**)&B, gB);
    cudaGetSymbolAddress((void**)&C, gC);

    const int rowBlocks = (NN + 63) / 64;
    const int nodeWarpBlocks = (NN * 32 + 255) / 256;

    // ---- CSR build; gemm64 L0 hoisted to launch index 3 (the profiled slot) --
    detect_k<<<1, 1>>>(ei);                                 // 0
    zerodeg_k<<<(NN + 255) / 256, 256>>>();                 // 1
    hist_k<<<(NE + 255) / 256, 256>>>(ei);                  // 2
    gemm64_k<<<rowBlocks, 256>>>(x, W0, A);                 // 3  <- profiled slot
    blocksum_k<<<SCAN_G, SCAN_B>>>();                       // 4
    blockscan_k<<<SCAN_G, SCAN_B>>>();                      // 5
    fill_k<<<(NE + 255) / 256, 256>>>(ei, ew);              // 6

    // ---- Layer 0 aggregation + softmax ----
    agg64sm_k<<<nodeWarpBlocks, 256>>>((const float2*)A, b0, (float2*)B);

    // ---- Layer 1 ----
    gemm64_k<<<rowBlocks, 256>>>(B, W1, A);
    agg64sm_k<<<nodeWarpBlocks, 256>>>((const float2*)A, b1, (float2*)B);

    // ---- Layer 2 (64 -> 10) ----
    gemm10_k<<<rowBlocks, 640>>>(B, W2, C);
    agg10sm_k<<<nodeWarpBlocks, 256>>>(C, b2, out);
}

// round 6
// speedup vs baseline: 1.5459x; 1.0405x over previous
#include <cuda_runtime.h>
#include <math.h>

#define NN 50000
#define NE 800000
#define HD 64
#define NC 10
#define SCAN_B 1024
#define SCAN_G ((NN + SCAN_B - 1) / SCAN_B)   // 49

// ---------------- scratch (device globals; no allocations allowed) ------------
__device__ __align__(256) float gA[NN * HD];
__device__ __align__(256) float gB[NN * HD];
__device__ __align__(256) float gC[NN * NC];
__device__ __align__(256) int2 g_ep[NE];   // packed (src, weight-bits), CSR order
__device__ int g_rowptr[NN + 1];
__device__ int g_fillpos[NN];
__device__ int g_deg[NN];
__device__ int g_part[SCAN_G];
__device__ int g_is64;

// ---------------- edge index dtype detect --------------------------------------
__global__ void detect_k(const void* ei) {
    if (threadIdx.x == 0 && blockIdx.x == 0) {
        const long long* p = (const long long*)ei;
        int ok = 1;
        for (int i = 0; i < 1024; i++) {
            long long v = p[i];
            if (v < 0 || v >= NN) { ok = 0; break; }
        }
        g_is64 = ok;
    }
}

__global__ void zerodeg_k() {
    int i = blockIdx.x * blockDim.x + threadIdx.x;
    if (i < NN) g_deg[i] = 0;
}

// histogram of destination degrees
__global__ void hist_k(const void* ei) {
    int i = blockIdx.x * blockDim.x + threadIdx.x;
    if (i >= NE) return;
    int d;
    if (g_is64) d = (int)((const long long*)ei)[NE + i];
    else        d = ((const int*)ei)[NE + i];
    atomicAdd(&g_deg[d], 1);
}

// ---- scan stage 1: per-block sums -------------------------------------------
__global__ void __launch_bounds__(SCAN_B) blocksum_k() {
    __shared__ int s[32];
    int idx = blockIdx.x * SCAN_B + threadIdx.x;
    int v = (idx < NN) ? g_deg[idx] : 0;
    #pragma unroll
    for (int o = 16; o; o >>= 1) v += __shfl_xor_sync(0xFFFFFFFFu, v, o);
    int lane = threadIdx.x & 31, warp = threadIdx.x >> 5;
    if (lane == 0) s[warp] = v;
    __syncthreads();
    if (warp == 0) {
        int w = s[lane];
        #pragma unroll
        for (int o = 16; o; o >>= 1) w += __shfl_xor_sync(0xFFFFFFFFu, w, o);
        if (lane == 0) g_part[blockIdx.x] = w;
    }
}

// ---- scan stage 2: per-block scan; each block redundantly scans partials -----
__global__ void __launch_bounds__(SCAN_B) blockscan_k() {
    __shared__ int parts[64];
    __shared__ int s[SCAN_B];
    int t = threadIdx.x;
    if (t < 64) parts[t] = (t < SCAN_G) ? g_part[t] : 0;
    __syncthreads();
    #pragma unroll
    for (int off = 1; off < 64; off <<= 1) {
        int v = (t < 64 && t >= off) ? parts[t - off] : 0;
        __syncthreads();
        if (t < 64) parts[t] += v;
        __syncthreads();
    }
    int blockoff = (blockIdx.x == 0) ? 0 : parts[blockIdx.x - 1];

    int idx = blockIdx.x * SCAN_B + t;
    int v = (idx < NN) ? g_deg[idx] : 0;
    s[t] = v;
    __syncthreads();
    #pragma unroll
    for (int off = 1; off < SCAN_B; off <<= 1) {
        int u = (t >= off) ? s[t - off] : 0;
        __syncthreads();
        s[t] += u;
        __syncthreads();
    }
    if (idx < NN) {
        int excl = blockoff + s[t] - v;
        g_rowptr[idx] = excl;
        g_fillpos[idx] = excl;
    }
    if (blockIdx.x == 0 && t == 0) g_rowptr[NN] = NE;
}

// scatter edges into packed CSR slots
__global__ void fill_k(const void* ei, const float* __restrict__ ew) {
    int i = blockIdx.x * blockDim.x + threadIdx.x;
    if (i >= NE) return;
    int sidx, d;
    if (g_is64) {
        const long long* p = (const long long*)ei;
        sidx = (int)p[i];
        d = (int)p[NE + i];
    } else {
        const int* p = (const int*)ei;
        sidx = p[i];
        d = p[NE + i];
    }
    int pos = atomicAdd(&g_fillpos[d], 1);
    g_ep[pos] = make_int2(sidx, __float_as_int(ew[i]));
}

// ---------------- GEMM: [NN,64] @ [64,64], 4x4 reg tile, float2 LDS -----------
__global__ void __launch_bounds__(256) gemm64_k(const float* __restrict__ in,
                                                const float* __restrict__ W,
                                                float* __restrict__ out) {
    __shared__ float Ws[64 * 64];
    __shared__ float Xs[64 * 64];
    int t = threadIdx.x;
    int row0 = blockIdx.x * 64;
    for (int i = t; i < 4096; i += 256) Ws[i] = W[i];
    for (int i = t; i < 4096; i += 256) {
        int r = row0 + (i >> 6);
        Xs[i] = (r < NN) ? in[r * 64 + (i & 63)] : 0.f;
    }
    __syncthreads();
    int c4 = (t & 15) * 4;   // column group: 4 consecutive cols
    int r4 = (t >> 4) * 4;   // row group:    4 consecutive rows
    float acc[4][4];
    #pragma unroll
    for (int i = 0; i < 4; i++)
        #pragma unroll
        for (int j = 0; j < 4; j++) acc[i][j] = 0.f;

    #pragma unroll 8
    for (int k = 0; k < 64; k += 2) {
        // weights for k and k+1, 4 cols each (2x float2 per k-row)
        float2 wa0 = *(const float2*)&Ws[k * 64 + c4];
        float2 wa1 = *(const float2*)&Ws[k * 64 + c4 + 2];
        float2 wb0 = *(const float2*)&Ws[(k + 1) * 64 + c4];
        float2 wb1 = *(const float2*)&Ws[(k + 1) * 64 + c4 + 2];
        // x pairs (k, k+1) for 4 rows
        float2 x0 = *(const float2*)&Xs[(r4 + 0) * 64 + k];
        float2 x1 = *(const float2*)&Xs[(r4 + 1) * 64 + k];
        float2 x2 = *(const float2*)&Xs[(r4 + 2) * 64 + k];
        float2 x3 = *(const float2*)&Xs[(r4 + 3) * 64 + k];

        acc[0][0] = fmaf(x0.x, wa0.x, fmaf(x0.y, wb0.x, acc[0][0]));
        acc[0][1] = fmaf(x0.x, wa0.y, fmaf(x0.y, wb0.y, acc[0][1]));
        acc[0][2] = fmaf(x0.x, wa1.x, fmaf(x0.y, wb1.x, acc[0][2]));
        acc[0][3] = fmaf(x0.x, wa1.y, fmaf(x0.y, wb1.y, acc[0][3]));

        acc[1][0] = fmaf(x1.x, wa0.x, fmaf(x1.y, wb0.x, acc[1][0]));
        acc[1][1] = fmaf(x1.x, wa0.y, fmaf(x1.y, wb0.y, acc[1][1]));
        acc[1][2] = fmaf(x1.x, wa1.x, fmaf(x1.y, wb1.x, acc[1][2]));
        acc[1][3] = fmaf(x1.x, wa1.y, fmaf(x1.y, wb1.y, acc[1][3]));

        acc[2][0] = fmaf(x2.x, wa0.x, fmaf(x2.y, wb0.x, acc[2][0]));
        acc[2][1] = fmaf(x2.x, wa0.y, fmaf(x2.y, wb0.y, acc[2][1]));
        acc[2][2] = fmaf(x2.x, wa1.x, fmaf(x2.y, wb1.x, acc[2][2]));
        acc[2][3] = fmaf(x2.x, wa1.y, fmaf(x2.y, wb1.y, acc[2][3]));

        acc[3][0] = fmaf(x3.x, wa0.x, fmaf(x3.y, wb0.x, acc[3][0]));
        acc[3][1] = fmaf(x3.x, wa0.y, fmaf(x3.y, wb0.y, acc[3][1]));
        acc[3][2] = fmaf(x3.x, wa1.x, fmaf(x3.y, wb1.x, acc[3][2]));
        acc[3][3] = fmaf(x3.x, wa1.y, fmaf(x3.y, wb1.y, acc[3][3]));
    }

    #pragma unroll
    for (int i = 0; i < 4; i++) {
        int r = row0 + r4 + i;
        if (r < NN) {
            float2* o2 = (float2*)&out[r * 64 + c4];
            o2[0] = make_float2(acc[i][0], acc[i][1]);
            o2[1] = make_float2(acc[i][2], acc[i][3]);
        }
    }
}

// ---------------- GEMM: [NN,64] @ [64,10] (verbatim) --------------------------
__global__ void __launch_bounds__(640) gemm10_k(const float* __restrict__ in,
                                                const float* __restrict__ W,
                                                float* __restrict__ out) {
    __shared__ float Ws[64 * NC];
    __shared__ float Xs[64 * 64];
    int t = threadIdx.x;
    int row0 = blockIdx.x * 64;
    for (int i = t; i < 64 * NC; i += 640) Ws[i] = W[i];
    for (int i = t; i < 4096; i += 640) {
        int r = row0 + (i >> 6);
        Xs[i] = (r < NN) ? in[r * 64 + (i & 63)] : 0.f;
    }
    __syncthreads();
    int row = t / NC;
    int col = t - row * NC;
    int r = row0 + row;
    if (r >= NN) return;
    float s = 0.f;
    #pragma unroll
    for (int k = 0; k < 64; k++) s = fmaf(Xs[row * 64 + k], Ws[k * NC + col], s);
    out[r * NC + col] = s;
}

// ------- fused gather-aggregate (64ch) + bias + softmax: warp per node --------
__global__ void __launch_bounds__(256) agg64sm_k(const float2* __restrict__ h2,
                                                 const float* __restrict__ b,
                                                 float2* __restrict__ out2) {
    int node = (blockIdx.x * blockDim.x + threadIdx.x) >> 5;
    int lane = threadIdx.x & 31;
    if (node >= NN) return;
    int start = g_rowptr[node];
    int end = g_rowptr[node + 1];
    float ax0 = b[lane * 2], ay0 = b[lane * 2 + 1];
    float ax1 = 0.f, ay1 = 0.f;
    for (int j0 = start; j0 < end; j0 += 32) {
        int j = j0 + lane;
        int sx = 0, wy = 0;
        if (j < end) { int2 ep = g_ep[j]; sx = ep.x; wy = ep.y; }
        int cnt = min(32, end - j0);
        int q = 0;
        for (; q + 2 <= cnt; q += 2) {
            int s0 = __shfl_sync(0xFFFFFFFFu, sx, q);
            float w0 = __int_as_float(__shfl_sync(0xFFFFFFFFu, wy, q));
            int s1 = __shfl_sync(0xFFFFFFFFu, sx, q + 1);
            float w1 = __int_as_float(__shfl_sync(0xFFFFFFFFu, wy, q + 1));
            float2 v0 = h2[s0 * 32 + lane];
            float2 v1 = h2[s1 * 32 + lane];
            ax0 = fmaf(v0.x, w0, ax0); ay0 = fmaf(v0.y, w0, ay0);
            ax1 = fmaf(v1.x, w1, ax1); ay1 = fmaf(v1.y, w1, ay1);
        }
        if (q < cnt) {
            int s0 = __shfl_sync(0xFFFFFFFFu, sx, q);
            float w0 = __int_as_float(__shfl_sync(0xFFFFFFFFu, wy, q));
            float2 v0 = h2[s0 * 32 + lane];
            ax0 = fmaf(v0.x, w0, ax0); ay0 = fmaf(v0.y, w0, ay0);
        }
    }
    float a0 = ax0 + ax1, a1 = ay0 + ay1;
    float m = fmaxf(a0, a1);
    #pragma unroll
    for (int o = 16; o; o >>= 1) m = fmaxf(m, __shfl_xor_sync(0xFFFFFFFFu, m, o));
    float e0 = __expf(a0 - m);
    float e1 = __expf(a1 - m);
    float sm = e0 + e1;
    #pragma unroll
    for (int o = 16; o; o >>= 1) sm += __shfl_xor_sync(0xFFFFFFFFu, sm, o);
    float inv = 1.f / sm;
    out2[node * 32 + lane] = make_float2(e0 * inv, e1 * inv);
}

// ------- fused gather-aggregate (10ch) + bias + softmax ------------------------
__global__ void __launch_bounds__(256) agg10sm_k(const float* __restrict__ h,
                                                 const float* __restrict__ b,
                                                 float* __restrict__ out) {
    int node = (blockIdx.x * blockDim.x + threadIdx.x) >> 5;
    int lane = threadIdx.x & 31;
    if (node >= NN) return;
    int start = g_rowptr[node];
    int end = g_rowptr[node + 1];
    float a = (lane < NC) ? b[lane] : -INFINITY;
    for (int j0 = start; j0 < end; j0 += 32) {
        int j = j0 + lane;
        int sx = 0, wy = 0;
        if (j < end) { int2 ep = g_ep[j]; sx = ep.x; wy = ep.y; }
        int cnt = min(32, end - j0);
        for (int q = 0; q < cnt; q++) {
            int ss = __shfl_sync(0xFFFFFFFFu, sx, q);
            float ww = __int_as_float(__shfl_sync(0xFFFFFFFFu, wy, q));
            if (lane < NC) a = fmaf(h[ss * NC + lane], ww, a);
        }
    }
    float m = a;
    #pragma unroll
    for (int o = 16; o; o >>= 1) m = fmaxf(m, __shfl_xor_sync(0xFFFFFFFFu, m, o));
    float e = (lane < NC) ? __expf(a - m) : 0.f;
    float sm = e;
    #pragma unroll
    for (int o = 16; o; o >>= 1) sm += __shfl_xor_sync(0xFFFFFFFFu, sm, o);
    if (lane < NC) out[node * NC + lane] = e / sm;
}

// ---------------- launch ------------------------------------------------------
extern "C" void kernel_launch(void* const* d_in, const int* in_sizes, int n_in,
                              void* d_out, int out_size) {
    const float* x  = (const float*)d_in[0];
    const void*  ei = d_in[1];
    const float* ew = (const float*)d_in[2];
    const float* W0 = (const float*)d_in[3];
    const float* b0 = (const float*)d_in[4];
    const float* W1 = (const float*)d_in[5];
    const float* b1 = (const float*)d_in[6];
    const float* W2 = (const float*)d_in[7];
    const float* b2 = (const float*)d_in[8];
    float* out = (float*)d_out;

    float *A, *B, *C;
    cudaGetSymbolAddress((void**)&A, gA);
    cudaGetSymbolAddress((void**)&B, gB);
    cudaGetSymbolAddress((void**)&C, gC);

    const int rowBlocks = (NN + 63) / 64;
    const int nodeWarpBlocks = (NN * 32 + 255) / 256;

    // ---- CSR build; gemm64 L0 at launch index 3 (the profiled slot) ----------
    detect_k<<<1, 1>>>(ei);                                 // 0
    zerodeg_k<<<(NN + 255) / 256, 256>>>();                 // 1
    hist_k<<<(NE + 255) / 256, 256>>>(ei);                  // 2
    gemm64_k<<<rowBlocks, 256>>>(x, W0, A);                 // 3  <- profiled slot
    blocksum_k<<<SCAN_G, SCAN_B>>>();                       // 4
    blockscan_k<<<SCAN_G, SCAN_B>>>();                      // 5
    fill_k<<<(NE + 255) / 256, 256>>>(ei, ew);              // 6

    // ---- Layer 0 aggregation + softmax ----
    agg64sm_k<<<nodeWarpBlocks, 256>>>((const float2*)A, b0, (float2*)B);

    // ---- Layer 1 ----
    gemm64_k<<<rowBlocks, 256>>>(B, W1, A);
    agg64sm_k<<<nodeWarpBlocks, 256>>>((const float2*)A, b1, (float2*)B);

    // ---- Layer 2 (64 -> 10) ----
    gemm10_k<<<rowBlocks, 640>>>(B, W2, C);
    agg10sm_k<<<nodeWarpBlocks, 256>>>(C, b2, out);
}